// round 1
// baseline (speedup 1.0000x reference)
#include <cuda_runtime.h>
#include <cuda_bf16.h>

// CTC loss forward (log-space) — one block per batch element.
// Lattice: S = 2L+1 states; strict sequential dependence over T steps.
// States split by parity: even (blank) states -> threads [0..128],
// odd (label) states -> threads [160..287]. Threads [129..159] idle (barrier only).

#define NEGF (-1e30f)
#define MAXB 1024

__device__ float g_per_ex[MAXB];

__global__ __launch_bounds__(288, 1)
void ctc_forward_kernel(const float* __restrict__ pred,     // (B, T, C)
                        const int*   __restrict__ targets,  // (B, L)
                        const int*   __restrict__ pred_lengths,   // (B,)
                        const int*   __restrict__ target_lengths, // (B,)
                        int T, int C, int L)
{
    // L <= 128 assumed (S <= 257)
    __shared__ float aE[2][130];   // even states s=2i stored at [i+1]; [0] = NEG sentinel
    __shared__ float aO[2][130];   // odd  states s=2i+1 stored at [i+1]; [0] = NEG sentinel

    const int b   = blockIdx.x;
    const int tid = threadIdx.x;

    // state mapping
    const bool isEven = (tid <= 2 * (L / 2 == 0 ? 0 : 0) + 0 + (tid <= L)) && (tid <= L); // placeholder, fixed below
    (void)isEven;

    // even states: i in [0, L]  (s = 2i, count L+1)
    // odd  states: i in [0, L-1] (s = 2i+1, count L)
    const bool ev = (tid <= L);          // threads 0..L handle even state i = tid
    const bool od = (tid >= 160) && (tid - 160 < L);  // threads 160..160+L-1 handle odd i
    const int  i  = ev ? tid : (od ? (tid - 160) : 0);
    const bool active = ev || od;

    // emission column for this state
    int col = 0;
    bool skip = false;
    if (od) {
        int lbl = targets[(size_t)b * L + i];
        col = lbl;
        int prev = (i >= 1) ? targets[(size_t)b * L + i - 1] : -1;
        skip = (lbl != 0) && (lbl != prev);
    }
    // base pointer for this thread's emission column at t=0
    const float* basep = pred + ((size_t)b * T) * C + col;

    // effective number of updated steps (freeze beyond pred_length)
    int pl = pred_lengths[b];
    if (pl < 1) pl = 1;
    const int Teff = (pl < T) ? pl : T;

    // ---- init ----
    if (tid < 2) {             // sentinels
        aE[tid][0] = NEGF;
        aO[tid][0] = NEGF;
    }
    if (ev) aE[0][i + 1] = (i == 0) ? __ldg(basep) : NEGF;   // alpha0 even
    if (od) aO[0][i + 1] = (i == 0) ? __ldg(basep) : NEGF;   // alpha0 odd

    // emission prefetch ring (4 deep)
    float er0 = 0.f, er1 = 0.f, er2 = 0.f, er3 = 0.f;
    if (active) {
        if (1 < Teff) er0 = __ldg(basep + (size_t)1 * C);
        if (2 < Teff) er1 = __ldg(basep + (size_t)2 * C);
        if (3 < Teff) er2 = __ldg(basep + (size_t)3 * C);
        if (4 < Teff) er3 = __ldg(basep + (size_t)4 * C);
    }
    __syncthreads();

    int rb = 0;

    // ---- main recursion: one __syncthreads per time step ----
    for (int t0 = 1; t0 < Teff; t0 += 4) {
        #pragma unroll
        for (int j = 0; j < 4; j++) {
            const int t = t0 + j;
            if (t < Teff) {
                float e = (j == 0) ? er0 : (j == 1) ? er1 : (j == 2) ? er2 : er3;
                const int tn = t + 4;
                float enew = 0.f;
                if (active && tn < Teff) enew = __ldg(basep + (size_t)tn * C);

                if (ev) {
                    float a1 = aE[rb][i + 1];
                    float a2 = aO[rb][i];
                    float m  = fmaxf(a1, a2);
                    float d  = fabsf(a1 - a2);
                    float v  = m + __logf(1.0f + __expf(-d)) + e;
                    aE[rb ^ 1][i + 1] = v;
                } else if (od) {
                    float a1 = aO[rb][i + 1];
                    float a2 = aE[rb][i + 1];
                    float a3 = skip ? aO[rb][i] : NEGF;
                    float m  = fmaxf(fmaxf(a1, a2), a3);
                    float sm = __expf(a1 - m) + __expf(a2 - m) + __expf(a3 - m);
                    float v  = m + __logf(sm) + e;
                    aO[rb ^ 1][i + 1] = v;
                }
                if (j == 0) er0 = enew; else if (j == 1) er1 = enew;
                else if (j == 2) er2 = enew; else er3 = enew;

                __syncthreads();
                rb ^= 1;
            }
        }
    }
    __syncthreads();

    // ---- per-example loss ----
    if (tid == 0) {
        int tl = target_lengths[b];
        int tlc = tl < 1 ? 1 : (tl > L ? L : tl);
        // alpha_T indices: 2*tl-1 (odd, i = tl-1 -> aO[tl]) and 2*tl (even, i = tl -> aE[tl+1])
        float l1 = aO[rb][tlc];
        float l2 = aE[rb][tlc + 1];
        float m  = fmaxf(l1, l2);
        float r  = m + __logf(__expf(l1 - m) + __expf(l2 - m));
        float per = -r;
        if (per > 1e29f) per = 0.0f;
        g_per_ex[b] = per / (float)(tl < 1 ? 1 : tl);
    }
}

__global__ void ctc_reduce_kernel(float* __restrict__ out, int B)
{
    __shared__ float sred[32];
    float v = 0.f;
    for (int idx = threadIdx.x; idx < B; idx += blockDim.x) v += g_per_ex[idx];
    #pragma unroll
    for (int o = 16; o > 0; o >>= 1) v += __shfl_down_sync(0xffffffffu, v, o);
    if ((threadIdx.x & 31) == 0) sred[threadIdx.x >> 5] = v;
    __syncthreads();
    if (threadIdx.x < 32) {
        int nw = (blockDim.x + 31) >> 5;
        float x = (threadIdx.x < nw) ? sred[threadIdx.x] : 0.f;
        #pragma unroll
        for (int o = 16; o > 0; o >>= 1) x += __shfl_down_sync(0xffffffffu, x, o);
        if (threadIdx.x == 0) out[0] = x / (float)B;
    }
}

extern "C" void kernel_launch(void* const* d_in, const int* in_sizes, int n_in,
                              void* d_out, int out_size)
{
    const float* pred            = (const float*)d_in[0];
    const int*   targets         = (const int*)d_in[1];
    const int*   pred_lengths    = (const int*)d_in[2];
    const int*   target_lengths  = (const int*)d_in[3];

    const int B = in_sizes[2];              // pred_lengths count
    const int L = in_sizes[1] / B;          // targets (B, L)
    const int C = 128;                      // fixed for this problem instance
    const int T = (in_sizes[0] / B) / C;    // predictions (B, T, C)

    ctc_forward_kernel<<<B, 288>>>(pred, targets, pred_lengths, target_lengths, T, C, L);
    ctc_reduce_kernel<<<1, 128>>>((float*)d_out, B);
}

// round 2
// speedup vs baseline: 1.8264x; 1.8264x over previous
#include <cuda_runtime.h>
#include <cuda_bf16.h>

// CTC forward, one block (128 threads) per batch element.
// Thread i owns lattice pair (E_i = state 2i, O_i = state 2i+1) in registers.
// Only O_{i-1} crosses threads -> 1 STS + 1 LDS + 1 barrier per time step.
// Thread 127 additionally owns E_128 (input O_127 is its own register).
// All alphas kept in log2 domain (emissions pre-scaled by log2(e)).

#define NEGF  (-1e30f)
#define LOG2E 1.4426950408889634f
#define LN2   0.6931471805599453f
#define MAXB  1024

__device__ float g_per_ex[MAXB];

__device__ __forceinline__ float lse2(float a, float b) {
    // log2(2^a + 2^b), MUFU-only chain
    float m = fmaxf(a, b);
    float d = fminf(a, b) - m;          // <= 0
    return m + __log2f(1.0f + exp2f(d));
}

__global__ __launch_bounds__(128, 1)
void ctc_forward_kernel(const float* __restrict__ pred,           // (B, T, C)
                        const int*   __restrict__ targets,        // (B, L)
                        const int*   __restrict__ pred_lengths,   // (B,)
                        const int*   __restrict__ target_lengths, // (B,)
                        int T, int C, int L)
{
    __shared__ float sO[2][130];   // O_{i} stored at [i+1]; [0] = NEG sentinel
    __shared__ float sE[130];      // final gather of E (129 values)

    const int b = blockIdx.x;
    const int i = threadIdx.x;     // pair index 0..127

    const int  li   = (i < L) ? i : (L - 1);
    const int  lbl  = targets[(size_t)b * L + li];
    const int  prev = (li >= 1) ? targets[(size_t)b * L + li - 1] : -1;
    const bool skip = (lbl != 0) && (lbl != prev);

    const float* rowp = pred + (size_t)b * T * C;

    int pl = pred_lengths[b];
    int Teff = pl < T ? pl : T; if (Teff < 1) Teff = 1;
    const int steps = Teff - 1;          // updates at t = 1..steps

    // ---- init (t = 0) ----
    float eb0 = __ldg(rowp) * LOG2E;
    float el0 = __ldg(rowp + lbl) * LOG2E;
    float E  = (i == 0) ? eb0 : NEGF;    // state 0
    float O  = (i == 0) ? el0 : NEGF;    // state 1
    float E2 = NEGF;                     // state 2L (thread 127)

    if (i == 0) { sO[0][0] = NEGF; sO[1][0] = NEGF; }
    sO[0][i + 1] = O;

    float pO  = lse2(O, E);              // precomputed own-part of O update
    float pE2 = lse2(E2, O);             // thread 127 only (O = O_127 own reg)

    // emission prefetch ring (4 deep), clamped indices
    float eb[4], el[4];
#pragma unroll
    for (int j = 0; j < 4; j++) {
        int tt = 1 + j; if (tt > steps) tt = steps; if (tt < 0) tt = 0;
        const float* p = rowp + (size_t)tt * C;
        eb[j] = __ldg(p) * LOG2E;
        el[j] = __ldg(p + lbl) * LOG2E;
    }

    __syncthreads();

    int t = 1;
    // ---- main loop: 4 steps / iteration, compile-time ping-pong ----
    for (; t + 3 <= steps; t += 4) {
#pragma unroll
        for (int j = 0; j < 4; j++) {
            const int rb = j & 1;                   // buf parity (starts 0 each iter)
            float Om1 = sO[rb][i];                  // O_{i-1} (sentinel at [0])
            float nO  = lse2(pO, skip ? Om1 : NEGF) + el[j];
            float nE  = lse2(E, Om1) + eb[j];
            sO[rb ^ 1][i + 1] = nO;
            if (i == 127) { E2 = pE2 + eb[j]; }     // lse2(E2,O_127) precomputed
            O = nO; E = nE;
            pO = lse2(O, E);
            if (i == 127) pE2 = lse2(E2, O);
            // prefetch step t+4+j
            int tt = t + 4 + j; if (tt > steps) tt = steps;
            const float* p = rowp + (size_t)tt * C;
            eb[j] = __ldg(p) * LOG2E;
            el[j] = __ldg(p + lbl) * LOG2E;
            __syncthreads();
        }
    }
    // ---- remainder (< 4 steps) ----
    {
        int rb = 0;
        for (int j = 0; t <= steps; t++, j++) {
            float Om1 = sO[rb][i];
            float nO  = lse2(pO, skip ? Om1 : NEGF) + el[j];
            float nE  = lse2(E, Om1) + eb[j];
            sO[rb ^ 1][i + 1] = nO;
            if (i == 127) { E2 = pE2 + eb[j]; }
            O = nO; E = nE;
            pO = lse2(O, E);
            if (i == 127) pE2 = lse2(E2, O);
            rb ^= 1;
            __syncthreads();
        }
        // final O values live in sO[rb] (last written buffer)
        sE[i] = E;
        if (i == 127) sE[128] = E2;
        __syncthreads();

        if (i == 0) {
            int tl = target_lengths[b];
            int tlc = tl; if (tlc < 1) tlc = 1; if (tlc > L) tlc = L;
            float l1 = sO[rb][tlc];      // O_{tl-1} at index (tl-1)+1
            float l2 = sE[tlc];          // E_{tl}
            float r  = lse2(l1, l2) * LN2;
            float per = -r;
            if (per > 1e29f) per = 0.0f;
            int denom = tl < 1 ? 1 : tl;
            g_per_ex[b] = per / (float)denom;
        }
    }
}

__global__ void ctc_reduce_kernel(float* __restrict__ out, int B)
{
    __shared__ float sred[32];
    float v = 0.f;
    for (int idx = threadIdx.x; idx < B; idx += blockDim.x) v += g_per_ex[idx];
#pragma unroll
    for (int o = 16; o > 0; o >>= 1) v += __shfl_down_sync(0xffffffffu, v, o);
    if ((threadIdx.x & 31) == 0) sred[threadIdx.x >> 5] = v;
    __syncthreads();
    if (threadIdx.x < 32) {
        int nw = (blockDim.x + 31) >> 5;
        float x = (threadIdx.x < nw) ? sred[threadIdx.x] : 0.f;
#pragma unroll
        for (int o = 16; o > 0; o >>= 1) x += __shfl_down_sync(0xffffffffu, x, o);
        if (threadIdx.x == 0) out[0] = x / (float)B;
    }
}

extern "C" void kernel_launch(void* const* d_in, const int* in_sizes, int n_in,
                              void* d_out, int out_size)
{
    const float* pred           = (const float*)d_in[0];
    const int*   targets        = (const int*)d_in[1];
    const int*   pred_lengths   = (const int*)d_in[2];
    const int*   target_lengths = (const int*)d_in[3];

    const int B = in_sizes[2];
    const int L = in_sizes[1] / B;
    const int C = 128;
    const int T = (in_sizes[0] / B) / C;

    ctc_forward_kernel<<<B, 128>>>(pred, targets, pred_lengths, target_lengths, T, C, L);
    ctc_reduce_kernel<<<1, 128>>>((float*)d_out, B);
}